// round 11
// baseline (speedup 1.0000x reference)
#include <cuda_runtime.h>
#include <math.h>
#include <stdint.h>

#define BS     32
#define TT     20               // targets per batch
#define GW     76               // grid width/height
#define PLANE  (GW*GW)          // 5776
#define CPB    (3*PLANE)        // cells per batch = 17328
#define HPB    (CPB/2)          // cell-pairs per batch = 8664
#define NCHUNK 34               // chunks of 256 pairs per batch
#define CPB_BLK 2               // chunks per block
#define BPB    17               // blocks per batch
#define MAIN_BLOCKS (BS*BPB)    // 544
#define TGT_BLOCKS  80          // 80 x 8 warps = 640 warps = BS*TT
#define GRID_TOT (MAIN_BLOCKS + TGT_BLOCKS)  // 624 -> single wave
#define NC     80

// scaled anchors = ANCHORS / 8
__constant__ float c_aw9[9] = {1.5f, 2.375f, 5.0f, 4.5f, 9.5f, 9.0f, 17.75f, 24.0f, 57.375f};
__constant__ float c_ah9[9] = {2.0f, 4.5f,  3.5f, 9.375f, 6.875f, 18.25f, 13.75f, 30.375f, 50.125f};
// level-2 anchors (mask [0,1,2])
__constant__ float c_aw3[3] = {1.5f, 2.375f, 5.0f};
__constant__ float c_ah3[3] = {2.0f, 4.5f,  3.5f};

// zero-init at load; finalizer resets after each run (graph-replay safe)
__device__ double       g_acc[5];   // 0:loc 1:nobj 2:cls 3:conf 4:mask
__device__ unsigned int g_done;

// softplus(z) = max(z,0)+log1p(exp(-|z|)) == -log(sigmoid(-z)); matches the
// clipped BCE exactly for |z| < 16.1 (clip never binds at these input scales)
__device__ __forceinline__ float softplusf_(float z) {
    float az = fabsf(z);
    return fmaxf(z, 0.0f) + __logf(1.0f + __expf(-az));
}
__device__ __forceinline__ float sigmoidf_(float x) {
    return __fdividef(1.0f, 1.0f + __expf(-x));
}

// prep one target: returns cell (-1 if not this level) and gt geometry
__device__ __forceinline__ int prep_target(const float* __restrict__ p,
                                           float& gx, float& gy, float& gw, float& gh) {
    gx = p[0] * (float)GW; gy = p[1] * (float)GW;
    gw = p[2] * (float)GW; gh = p[3] * (float)GW;
    float bestr = -1e30f; int best = 0;
    #pragma unroll
    for (int n = 0; n < 9; n++) {
        float inter = fminf(gw, c_aw9[n]) * fminf(gh, c_ah9[n]);
        float uni   = gw * gh + c_aw9[n] * c_ah9[n] - inter;
        float r = inter / uni;   // exact divide: argmax ties matter
        if (r > bestr) { bestr = r; best = n; }
    }
    if (best >= 3) return -1;    // l=2: anchors_mask [0,1,2]
    int gi = min(max((int)floorf(gx), 0), GW - 1);
    int gj = min(max((int)floorf(gy), 0), GW - 1);
    return best * PLANE + gj * GW + gi;
}

__device__ __forceinline__ void finish_block(float* out) {
    __syncthreads();
    if (threadIdx.x == 0) {
        __threadfence();
        unsigned int v = atomicAdd(&g_done, 1u);
        if (v == GRID_TOT - 1) {
            __threadfence();
            double a0 = g_acc[0], a1 = g_acc[1], a2 = g_acc[2];
            double a3 = g_acc[3], a4 = g_acc[4];
            g_acc[0]=0.0; g_acc[1]=0.0; g_acc[2]=0.0; g_acc[3]=0.0; g_acc[4]=0.0;
            g_done = 0u;
            double n     = a1 > 1.0 ? a1 : 1.0;
            double cmask = a4 > 1.0 ? a4 : 1.0;
            const double OBJ_RATIO = 5.0 * 608.0 * 608.0 / (416.0 * 416.0);
            const double BAL = 4.0;   // BALANCE[2]
            double loss = a0 / n * 0.05
                        + a2 / (n * (double)NC)
                        + a3 / cmask * BAL * OBJ_RATIO;
            out[0] = (float)loss;
        }
    }
}

__global__ void __launch_bounds__(256) k_fused(const float* __restrict__ in,
                                               const float* __restrict__ tgt,
                                               float* __restrict__ out)
{
    const int tid = threadIdx.x;

    if (blockIdx.x < MAIN_BLOCKS) {
        // ===== main path: conf BCE + ignore, 2 cells/thread, 2 chunks/block =====
        __shared__ float4 s_box[TT];   // gt corners x0,y0,x1,y1
        __shared__ float  s_ar[TT];    // gw*gh
        __shared__ int    s_cell[TT];

        const int b = blockIdx.x / BPB;

        if (tid < TT) {
            float gx, gy, gw, gh;
            int cell = prep_target(tgt + (b * TT + tid) * 5, gx, gy, gw, gh);
            s_box[tid] = make_float4(gx - 0.5f * gw, gy - 0.5f * gh,
                                     gx + 0.5f * gw, gy + 0.5f * gh);
            s_ar[tid]  = gw * gh;
            s_cell[tid] = cell;
        }
        __syncthreads();

        float cl = 0.0f, cm = 0.0f;
        const int ck0 = (blockIdx.x % BPB) * CPB_BLK;
        #pragma unroll 1
        for (int ck = ck0; ck < ck0 + CPB_BLK; ck++) {
            int pr = ck * 256 + tid;
            if (pr >= HPB) break;
            int c0   = 2 * pr;
            int a    = c0 / PLANE;
            int rem0 = c0 - a * PLANE;
            int rem1 = rem0 + 1;
            int i0 = rem0 % GW, j0 = rem0 / GW;
            int i1 = rem1 % GW, j1 = rem1 / GW;

            const float* base = in + ((b * 255 + a * 85) * PLANE + rem0);
            float2 rx = *(const float2*)(base);
            float2 ry = *(const float2*)(base + PLANE);
            float2 rw = *(const float2*)(base + 2 * PLANE);
            float2 rh = *(const float2*)(base + 3 * PLANE);
            float2 rc = *(const float2*)(base + 4 * PLANE);

            float aw = c_aw3[a], ah = c_ah3[a];
            float px0 = (float)i0 + sigmoidf_(rx.x), py0 = (float)j0 + sigmoidf_(ry.x);
            float px1 = (float)i1 + sigmoidf_(rx.y), py1 = (float)j1 + sigmoidf_(ry.y);
            float pw0 = __expf(rw.x) * aw, ph0 = __expf(rh.x) * ah;
            float pw1 = __expf(rw.y) * aw, ph1 = __expf(rh.y) * ah;

            float a0x = px0 - 0.5f * pw0, b0x = px0 + 0.5f * pw0;
            float a0y = py0 - 0.5f * ph0, b0y = py0 + 0.5f * ph0;
            float a1x = px1 - 0.5f * pw1, b1x = px1 + 0.5f * pw1;
            float a1y = py1 - 0.5f * ph1, b1y = py1 + 0.5f * ph1;
            float pa0 = pw0 * ph0, pa1 = pw1 * ph1;

            // ignore margin (iou>0.5 <=> 3*inter > ga+pa) + obj membership
            float m0 = -1e30f, m1 = -1e30f;
            bool o0 = false, o1 = false;
            #pragma unroll
            for (int t = 0; t < TT; t++) {
                float4 bb = s_box[t];
                float ga  = s_ar[t];
                int   tc  = s_cell[t];

                float iw0 = fmaxf(fminf(bb.z, b0x) - fmaxf(bb.x, a0x), 0.0f);
                float ih0 = fmaxf(fminf(bb.w, b0y) - fmaxf(bb.y, a0y), 0.0f);
                m0 = fmaxf(m0, fmaf(3.0f, iw0 * ih0, -(ga + pa0)));
                o0 = o0 || (tc == c0);

                float iw1 = fmaxf(fminf(bb.z, b1x) - fmaxf(bb.x, a1x), 0.0f);
                float ih1 = fmaxf(fminf(bb.w, b1y) - fmaxf(bb.y, a1y), 0.0f);
                m1 = fmaxf(m1, fmaf(3.0f, iw1 * ih1, -(ga + pa1)));
                o1 = o1 || (tc == c0 + 1);
            }

            if (o0)              { cl += softplusf_(-rc.x); cm += 1.0f; }
            else if (m0 <= 0.0f) { cl += softplusf_( rc.x); cm += 1.0f; }
            if (o1)              { cl += softplusf_(-rc.y); cm += 1.0f; }
            else if (m1 <= 0.0f) { cl += softplusf_( rc.y); cm += 1.0f; }
        }

        #pragma unroll
        for (int o = 16; o > 0; o >>= 1) {
            cl += __shfl_down_sync(0xffffffffu, cl, o);
            cm += __shfl_down_sync(0xffffffffu, cm, o);
        }
        __shared__ float wcl[8], wcm[8];
        int wid = tid >> 5;
        if ((tid & 31) == 0) { wcl[wid] = cl; wcm[wid] = cm; }
        __syncthreads();
        if (tid == 0) {
            float scl = 0.0f, scm = 0.0f;
            #pragma unroll
            for (int k = 0; k < 8; k++) { scl += wcl[k]; scm += wcm[k]; }
            atomicAdd(&g_acc[3], (double)scl);
            atomicAdd(&g_acc[4], (double)scm);
        }
    } else {
        // ================= target path: one warp per target ================
        int t_idx = (blockIdx.x - MAIN_BLOCKS) * 8 + (tid >> 5);  // 0..639
        int lane  = tid & 31;

        // all lanes compute prep redundantly (no divergence, trivially cheap)
        float gx, gy, gw, gh;
        int cell = prep_target(tgt + t_idx * 5, gx, gy, gw, gh);

        if (cell >= 0) {
            int b   = t_idx / TT;
            int a   = cell / PLANE;
            int rem = cell - a * PLANE;
            const float* base = in + ((b * 255 + a * 85) * PLANE + rem);

            // class BCE: lanes cover 80 channels (<=3 each)
            int gc = (int)tgt[t_idx * 5 + 4];
            float cls = 0.0f;
            #pragma unroll
            for (int k = 0; k < 3; k++) {
                int ch = lane + 32 * k;
                if (ch < NC) {
                    float z = base[(5 + ch) * PLANE];
                    cls += (ch == gc) ? softplusf_(-z) : softplusf_(z);
                }
            }
            #pragma unroll
            for (int o = 16; o > 0; o >>= 1)
                cls += __shfl_down_sync(0xffffffffu, cls, o);

            if (lane == 0) {
                int i = rem % GW, j = rem / GW;
                float px = (float)i + sigmoidf_(base[0]);
                float py = (float)j + sigmoidf_(base[PLANE]);
                float pw = __expf(base[2 * PLANE]) * c_aw3[a];
                float ph = __expf(base[3 * PLANE]) * c_ah3[a];

                float p0x = px - 0.5f * pw, p1x = px + 0.5f * pw;
                float p0y = py - 0.5f * ph, p1y = py + 0.5f * ph;
                float q0x = gx - 0.5f * gw, q1x = gx + 0.5f * gw;
                float q0y = gy - 0.5f * gh, q1y = gy + 0.5f * gh;

                float iw = fmaxf(fminf(p1x, q1x) - fmaxf(p0x, q0x), 0.0f);
                float ih = fmaxf(fminf(p1y, q1y) - fmaxf(p0y, q0y), 0.0f);
                float inter = iw * ih;
                float uni = fmaxf(pw * ph + gw * gh - inter, 1e-6f);
                float iou = inter / uni;

                float dx = px - gx, dy = py - gy;
                float cd = dx * dx + dy * dy;
                float ew = fmaxf(fmaxf(p1x, q1x) - fminf(p0x, q0x), 0.0f);
                float eh = fmaxf(fmaxf(p1y, q1y) - fminf(p0y, q0y), 0.0f);
                float diag = fmaxf(ew * ew + eh * eh, 1e-6f);
                float ciou = iou - cd / diag;

                float dv = atanf(pw / fmaxf(ph, 1e-6f)) - atanf(gw / fmaxf(gh, 1e-6f));
                float v = 0.4052847345693511f * dv * dv;   // 4/pi^2
                float alpha = v / fmaxf(1.0f - iou + v, 1e-6f);
                ciou -= alpha * v;

                atomicAdd(&g_acc[0], (double)(1.0f - ciou));
                atomicAdd(&g_acc[1], 1.0);
                atomicAdd(&g_acc[2], (double)cls);
            }
        }
    }

    finish_block(out);
}

extern "C" void kernel_launch(void* const* d_in, const int* in_sizes, int n_in,
                              void* d_out, int out_size) {
    const float* in  = (const float*)d_in[0];
    const float* tgt = (const float*)d_in[1];
    float* out = (float*)d_out;
    k_fused<<<GRID_TOT, 256>>>(in, tgt, out);
}

// round 13
// speedup vs baseline: 1.5878x; 1.5878x over previous
#include <cuda_runtime.h>
#include <math.h>
#include <stdint.h>

#define BS     32
#define TT     20               // targets per batch
#define GW     76               // grid width/height
#define PLANE  (GW*GW)          // 5776
#define QPB    (3*PLANE/4)      // cell-quads per batch = 4332
#define BPB    17               // blocks per batch = ceil(4332/256)
#define MAIN_BLOCKS (BS*BPB)    // 544
#define TGT_BLOCKS  80          // 80 x 8 warps = 640 warps = BS*TT
#define GRID_TOT (MAIN_BLOCKS + TGT_BLOCKS)  // 624 -> single wave
#define NC     80

// scaled anchors = ANCHORS / 8
__constant__ float c_aw9[9] = {1.5f, 2.375f, 5.0f, 4.5f, 9.5f, 9.0f, 17.75f, 24.0f, 57.375f};
__constant__ float c_ah9[9] = {2.0f, 4.5f,  3.5f, 9.375f, 6.875f, 18.25f, 13.75f, 30.375f, 50.125f};
// level-2 anchors (mask [0,1,2])
__constant__ float c_aw3[3] = {1.5f, 2.375f, 5.0f};
__constant__ float c_ah3[3] = {2.0f, 4.5f,  3.5f};

// zero-init at load; finalizer resets after each run (graph-replay safe)
__device__ double       g_acc[5];   // 0:loc 1:nobj 2:cls 3:conf 4:mask
__device__ unsigned int g_done;

// softplus(z) = max(z,0)+log1p(exp(-|z|)) == -log(sigmoid(-z)); matches the
// clipped BCE exactly for |z| < 16.1 (clip never binds at these input scales)
__device__ __forceinline__ float softplusf_(float z) {
    float az = fabsf(z);
    return fmaxf(z, 0.0f) + __logf(1.0f + __expf(-az));
}
__device__ __forceinline__ float sigmoidf_(float x) {
    return __fdividef(1.0f, 1.0f + __expf(-x));
}

// prep one target: returns cell (-1 if not this level) and gt geometry
__device__ __forceinline__ int prep_target(const float* __restrict__ p,
                                           float& gx, float& gy, float& gw, float& gh) {
    gx = p[0] * (float)GW; gy = p[1] * (float)GW;
    gw = p[2] * (float)GW; gh = p[3] * (float)GW;
    float bestr = -1e30f; int best = 0;
    #pragma unroll
    for (int n = 0; n < 9; n++) {
        float inter = fminf(gw, c_aw9[n]) * fminf(gh, c_ah9[n]);
        float uni   = gw * gh + c_aw9[n] * c_ah9[n] - inter;
        float r = inter / uni;   // exact divide: argmax ties matter
        if (r > bestr) { bestr = r; best = n; }
    }
    if (best >= 3) return -1;    // l=2: anchors_mask [0,1,2]
    int gi = min(max((int)floorf(gx), 0), GW - 1);
    int gj = min(max((int)floorf(gy), 0), GW - 1);
    return best * PLANE + gj * GW + gi;
}

__device__ __forceinline__ void finish_block(float* out) {
    __syncthreads();
    if (threadIdx.x == 0) {
        __threadfence();
        unsigned int v = atomicAdd(&g_done, 1u);
        if (v == GRID_TOT - 1) {
            __threadfence();
            double a0 = g_acc[0], a1 = g_acc[1], a2 = g_acc[2];
            double a3 = g_acc[3], a4 = g_acc[4];
            g_acc[0]=0.0; g_acc[1]=0.0; g_acc[2]=0.0; g_acc[3]=0.0; g_acc[4]=0.0;
            g_done = 0u;
            double n     = a1 > 1.0 ? a1 : 1.0;
            double cmask = a4 > 1.0 ? a4 : 1.0;
            const double OBJ_RATIO = 5.0 * 608.0 * 608.0 / (416.0 * 416.0);
            const double BAL = 4.0;   // BALANCE[2]
            double loss = a0 / n * 0.05
                        + a2 / (n * (double)NC)
                        + a3 / cmask * BAL * OBJ_RATIO;
            out[0] = (float)loss;
        }
    }
}

__global__ void __launch_bounds__(256) k_fused(const float* __restrict__ in,
                                               const float* __restrict__ tgt,
                                               float* __restrict__ out)
{
    const int tid = threadIdx.x;

    if (blockIdx.x < MAIN_BLOCKS) {
        // ===== main path: conf BCE + ignore, 4 cells/thread (straight-line) =====
        __shared__ float4 s_box[TT];   // gt corners x0,y0,x1,y1
        __shared__ float  s_ar[TT];    // gw*gh
        __shared__ int    s_cell[TT];

        const int b = blockIdx.x / BPB;
        const int q = (blockIdx.x % BPB) * 256 + tid;

        if (tid < TT) {
            float gx, gy, gw, gh;
            int cell = prep_target(tgt + (b * TT + tid) * 5, gx, gy, gw, gh);
            s_box[tid] = make_float4(gx - 0.5f * gw, gy - 0.5f * gh,
                                     gx + 0.5f * gw, gy + 0.5f * gh);
            s_ar[tid]  = gw * gh;
            s_cell[tid] = cell;
        }
        __syncthreads();

        float cl = 0.0f, cm = 0.0f;
        if (q < QPB) {
            int c0  = 4 * q;
            int a   = c0 / PLANE;
            int rem = c0 - a * PLANE;            // multiple of 4; row-aligned (GW%4==0)
            int j   = rem / GW;
            int i0  = rem - j * GW;

            const float* base = in + ((b * 255 + a * 85) * PLANE + rem);
            float4 rx = *(const float4*)(base);
            float4 ry = *(const float4*)(base + PLANE);
            float4 rw = *(const float4*)(base + 2 * PLANE);
            float4 rh = *(const float4*)(base + 3 * PLANE);
            float4 rc = *(const float4*)(base + 4 * PLANE);

            const float aw = c_aw3[a], ah = c_ah3[a];
            const float fj = (float)j;

            // decode 4 cells
            float px0 = (float)(i0+0) + sigmoidf_(rx.x);
            float px1 = (float)(i0+1) + sigmoidf_(rx.y);
            float px2 = (float)(i0+2) + sigmoidf_(rx.z);
            float px3 = (float)(i0+3) + sigmoidf_(rx.w);
            float py0 = fj + sigmoidf_(ry.x);
            float py1 = fj + sigmoidf_(ry.y);
            float py2 = fj + sigmoidf_(ry.z);
            float py3 = fj + sigmoidf_(ry.w);
            float pw0 = __expf(rw.x) * aw, pw1 = __expf(rw.y) * aw;
            float pw2 = __expf(rw.z) * aw, pw3 = __expf(rw.w) * aw;
            float ph0 = __expf(rh.x) * ah, ph1 = __expf(rh.y) * ah;
            float ph2 = __expf(rh.z) * ah, ph3 = __expf(rh.w) * ah;

            float l0x = px0 - 0.5f*pw0, r0x = px0 + 0.5f*pw0;
            float l1x = px1 - 0.5f*pw1, r1x = px1 + 0.5f*pw1;
            float l2x = px2 - 0.5f*pw2, r2x = px2 + 0.5f*pw2;
            float l3x = px3 - 0.5f*pw3, r3x = px3 + 0.5f*pw3;
            float l0y = py0 - 0.5f*ph0, r0y = py0 + 0.5f*ph0;
            float l1y = py1 - 0.5f*ph1, r1y = py1 + 0.5f*ph1;
            float l2y = py2 - 0.5f*ph2, r2y = py2 + 0.5f*ph2;
            float l3y = py3 - 0.5f*ph3, r3y = py3 + 0.5f*ph3;
            float pa0 = pw0*ph0, pa1 = pw1*ph1, pa2 = pw2*ph2, pa3 = pw3*ph3;

            // ignore margins (iou>0.5 <=> 3*inter > ga+pa) + obj bitmask
            float m0 = -1e30f, m1 = -1e30f, m2 = -1e30f, m3 = -1e30f;
            unsigned bits = 0u;
            #pragma unroll
            for (int t = 0; t < TT; t++) {
                float4 bb = s_box[t];
                float ga  = s_ar[t];
                int d = s_cell[t] - c0;
                if ((unsigned)d < 4u) bits |= 1u << d;

                float iw0 = fmaxf(fminf(bb.z, r0x) - fmaxf(bb.x, l0x), 0.0f);
                float ih0 = fmaxf(fminf(bb.w, r0y) - fmaxf(bb.y, l0y), 0.0f);
                m0 = fmaxf(m0, fmaf(3.0f, iw0*ih0, -(ga + pa0)));

                float iw1 = fmaxf(fminf(bb.z, r1x) - fmaxf(bb.x, l1x), 0.0f);
                float ih1 = fmaxf(fminf(bb.w, r1y) - fmaxf(bb.y, l1y), 0.0f);
                m1 = fmaxf(m1, fmaf(3.0f, iw1*ih1, -(ga + pa1)));

                float iw2 = fmaxf(fminf(bb.z, r2x) - fmaxf(bb.x, l2x), 0.0f);
                float ih2 = fmaxf(fminf(bb.w, r2y) - fmaxf(bb.y, l2y), 0.0f);
                m2 = fmaxf(m2, fmaf(3.0f, iw2*ih2, -(ga + pa2)));

                float iw3 = fmaxf(fminf(bb.z, r3x) - fmaxf(bb.x, l3x), 0.0f);
                float ih3 = fmaxf(fminf(bb.w, r3y) - fmaxf(bb.y, l3y), 0.0f);
                m3 = fmaxf(m3, fmaf(3.0f, iw3*ih3, -(ga + pa3)));
            }

            if (bits & 1u)       { cl += softplusf_(-rc.x); cm += 1.0f; }
            else if (m0 <= 0.0f) { cl += softplusf_( rc.x); cm += 1.0f; }
            if (bits & 2u)       { cl += softplusf_(-rc.y); cm += 1.0f; }
            else if (m1 <= 0.0f) { cl += softplusf_( rc.y); cm += 1.0f; }
            if (bits & 4u)       { cl += softplusf_(-rc.z); cm += 1.0f; }
            else if (m2 <= 0.0f) { cl += softplusf_( rc.z); cm += 1.0f; }
            if (bits & 8u)       { cl += softplusf_(-rc.w); cm += 1.0f; }
            else if (m3 <= 0.0f) { cl += softplusf_( rc.w); cm += 1.0f; }
        }

        #pragma unroll
        for (int o = 16; o > 0; o >>= 1) {
            cl += __shfl_down_sync(0xffffffffu, cl, o);
            cm += __shfl_down_sync(0xffffffffu, cm, o);
        }
        __shared__ float wcl[8], wcm[8];
        int wid = tid >> 5;
        if ((tid & 31) == 0) { wcl[wid] = cl; wcm[wid] = cm; }
        __syncthreads();
        if (tid == 0) {
            float scl = 0.0f, scm = 0.0f;
            #pragma unroll
            for (int k = 0; k < 8; k++) { scl += wcl[k]; scm += wcm[k]; }
            atomicAdd(&g_acc[3], (double)scl);
            atomicAdd(&g_acc[4], (double)scm);
        }
    } else {
        // ================= target path: one warp per target ================
        int t_idx = (blockIdx.x - MAIN_BLOCKS) * 8 + (tid >> 5);  // 0..639
        int lane  = tid & 31;

        // all lanes compute prep redundantly (no divergence, trivially cheap)
        float gx, gy, gw, gh;
        int cell = prep_target(tgt + t_idx * 5, gx, gy, gw, gh);

        if (cell >= 0) {
            int b   = t_idx / TT;
            int a   = cell / PLANE;
            int rem = cell - a * PLANE;
            const float* base = in + ((b * 255 + a * 85) * PLANE + rem);

            // class BCE: lanes cover 80 channels (<=3 each)
            int gc = (int)tgt[t_idx * 5 + 4];
            float cls = 0.0f;
            #pragma unroll
            for (int k = 0; k < 3; k++) {
                int ch = lane + 32 * k;
                if (ch < NC) {
                    float z = base[(5 + ch) * PLANE];
                    cls += (ch == gc) ? softplusf_(-z) : softplusf_(z);
                }
            }
            #pragma unroll
            for (int o = 16; o > 0; o >>= 1)
                cls += __shfl_down_sync(0xffffffffu, cls, o);

            if (lane == 0) {
                int i = rem % GW, j = rem / GW;
                float px = (float)i + sigmoidf_(base[0]);
                float py = (float)j + sigmoidf_(base[PLANE]);
                float pw = __expf(base[2 * PLANE]) * c_aw3[a];
                float ph = __expf(base[3 * PLANE]) * c_ah3[a];

                float p0x = px - 0.5f * pw, p1x = px + 0.5f * pw;
                float p0y = py - 0.5f * ph, p1y = py + 0.5f * ph;
                float q0x = gx - 0.5f * gw, q1x = gx + 0.5f * gw;
                float q0y = gy - 0.5f * gh, q1y = gy + 0.5f * gh;

                float iw = fmaxf(fminf(p1x, q1x) - fmaxf(p0x, q0x), 0.0f);
                float ih = fmaxf(fminf(p1y, q1y) - fmaxf(p0y, q0y), 0.0f);
                float inter = iw * ih;
                float uni = fmaxf(pw * ph + gw * gh - inter, 1e-6f);
                float iou = inter / uni;

                float dx = px - gx, dy = py - gy;
                float cd = dx * dx + dy * dy;
                float ew = fmaxf(fmaxf(p1x, q1x) - fminf(p0x, q0x), 0.0f);
                float eh = fmaxf(fmaxf(p1y, q1y) - fminf(p0y, q0y), 0.0f);
                float diag = fmaxf(ew * ew + eh * eh, 1e-6f);
                float ciou = iou - cd / diag;

                float dv = atanf(pw / fmaxf(ph, 1e-6f)) - atanf(gw / fmaxf(gh, 1e-6f));
                float v = 0.4052847345693511f * dv * dv;   // 4/pi^2
                float alpha = v / fmaxf(1.0f - iou + v, 1e-6f);
                ciou -= alpha * v;

                atomicAdd(&g_acc[0], (double)(1.0f - ciou));
                atomicAdd(&g_acc[1], 1.0);
                atomicAdd(&g_acc[2], (double)cls);
            }
        }
    }

    finish_block(out);
}

extern "C" void kernel_launch(void* const* d_in, const int* in_sizes, int n_in,
                              void* d_out, int out_size) {
    const float* in  = (const float*)d_in[0];
    const float* tgt = (const float*)d_in[1];
    float* out = (float*)d_out;
    k_fused<<<GRID_TOT, 256>>>(in, tgt, out);
}